// round 1
// baseline (speedup 1.0000x reference)
#include <cuda_runtime.h>
#include <cstdint>

// Problem shape (fixed by reference): B=4, T=2048, C=2048, H=16, d=128
#define BATCH 4
#define TQ    2048
#define CH    2048
#define NHEAD 16
#define HDIM  128
#define C3    (3*CH)   // 6144

// Scratch (device globals -- no allocation allowed)
__device__ float g_qkv[(size_t)BATCH * TQ * C3];            // 201 MB
__device__ float g_att[(size_t)BATCH * NHEAD * TQ * TQ];    // 1 GB
__device__ float g_out[(size_t)BATCH * TQ * CH];            // 67 MB

__device__ __forceinline__ float f2tf32(float x) {
    uint32_t u;
    asm("cvt.rna.tf32.f32 %0, %1;" : "=r"(u) : "f"(x));
    return __uint_as_float(u);
}

// ---------------------------------------------------------------------------
// Generic tiled tf32 tensor-core GEMM.
//   C[M,N] = A[M,K] * op(B)      (fp32 in/out, tf32 mma, fp32 accumulate)
//   BNT=true : B is [N,K] row-major (C = A * B^T)   -- "NT"
//   BNT=false: B is [K,N] row-major (C = A * B)     -- "NN"
//   CSKIP : skip blocks with blockIdx.x > blockIdx.y (causal upper blocks)
//   CK    : effective K = (blockIdx.y+1)*128 (causal K truncation for P*V)
// blockIdx.z batches over (b,h): offsets off = (z>>4)*s1 + (z&15)*s2.
// Tile: 128x128x32, 256 threads, warps 2(m) x 4(n), each warp 64x32.
// All dims are exact multiples of the tile -- no bounds checks needed.
// ---------------------------------------------------------------------------
template<bool BNT, bool CSKIP, bool CK>
__global__ void gemm_tc(const float* __restrict__ A, int lda, size_t sA1, size_t sA2,
                        const float* __restrict__ B, int ldb, size_t sB1, size_t sB2,
                        float*       __restrict__ C, int ldc, size_t sC1, size_t sC2,
                        int K)
{
    if (CSKIP && blockIdx.x > blockIdx.y) return;

    const int z  = blockIdx.z;
    const int zb = z >> 4;
    const int zh = z & 15;

    const float* Ab = A + zb * sA1 + zh * sA2 + (size_t)blockIdx.y * 128 * (size_t)lda;
    const float* Bb = B + zb * sB1 + zh * sB2
                        + (BNT ? (size_t)blockIdx.x * 128 * (size_t)ldb
                               : (size_t)blockIdx.x * 128);
    float*       Cb = C + zb * sC1 + zh * sC2
                        + (size_t)blockIdx.y * 128 * (size_t)ldc
                        + (size_t)blockIdx.x * 128;

    const int Keff = CK ? (int)(blockIdx.y + 1) * 128 : K;

    // A: [128][32] padded to 36 floats/row (conflict-free fragment loads)
    __shared__ float As[128][36];
    // B: NT -> [128 n][36], NN -> [32 k][136]
    __shared__ float Bs[BNT ? (128 * 36) : (32 * 136)];

    const int tid  = threadIdx.x;
    const int wid  = tid >> 5;
    const int lane = tid & 31;
    const int wm   = (wid & 1) * 64;   // warp m-offset
    const int wn   = (wid >> 1) * 32;  // warp n-offset
    const int g    = lane >> 2;        // groupID
    const int t    = lane & 3;         // threadID_in_group

    float acc[4][4][4];
#pragma unroll
    for (int i = 0; i < 4; i++)
#pragma unroll
        for (int j = 0; j < 4; j++)
#pragma unroll
            for (int r = 0; r < 4; r++) acc[i][j][r] = 0.f;

    for (int kt = 0; kt < Keff; kt += 32) {
        // --- load A tile: 128x32 floats, tf32-rounded once here ---
#pragma unroll
        for (int i = 0; i < 4; i++) {
            int idx = tid + i * 256;
            int r   = idx >> 3;
            int c4  = (idx & 7) << 2;
            float4 v = *(const float4*)(Ab + (size_t)r * lda + kt + c4);
            v.x = f2tf32(v.x); v.y = f2tf32(v.y); v.z = f2tf32(v.z); v.w = f2tf32(v.w);
            *(float4*)&As[r][c4] = v;
        }
        // --- load B tile ---
#pragma unroll
        for (int i = 0; i < 4; i++) {
            int idx = tid + i * 256;
            if (BNT) {
                int r  = idx >> 3;          // n row (128)
                int c4 = (idx & 7) << 2;    // k col
                float4 v = *(const float4*)(Bb + (size_t)r * ldb + kt + c4);
                v.x = f2tf32(v.x); v.y = f2tf32(v.y); v.z = f2tf32(v.z); v.w = f2tf32(v.w);
                *(float4*)&Bs[r * 36 + c4] = v;
            } else {
                int r  = idx >> 5;          // k row (32)
                int c4 = (idx & 31) << 2;   // n col (128)
                float4 v = *(const float4*)(Bb + (size_t)(kt + r) * ldb + c4);
                v.x = f2tf32(v.x); v.y = f2tf32(v.y); v.z = f2tf32(v.z); v.w = f2tf32(v.w);
                *(float4*)&Bs[r * 136 + c4] = v;
            }
        }
        __syncthreads();

#pragma unroll
        for (int kk = 0; kk < 4; kk++) {
            const int k0 = kk * 8;
            uint32_t af[4][4], bf[4][2];
#pragma unroll
            for (int mt = 0; mt < 4; mt++) {
                int row = wm + mt * 16 + g;
                af[mt][0] = __float_as_uint(As[row    ][k0 + t    ]);
                af[mt][1] = __float_as_uint(As[row + 8][k0 + t    ]);
                af[mt][2] = __float_as_uint(As[row    ][k0 + t + 4]);
                af[mt][3] = __float_as_uint(As[row + 8][k0 + t + 4]);
            }
#pragma unroll
            for (int nt = 0; nt < 4; nt++) {
                int col = wn + nt * 8 + g;
                if (BNT) {
                    bf[nt][0] = __float_as_uint(Bs[col * 36 + k0 + t    ]);
                    bf[nt][1] = __float_as_uint(Bs[col * 36 + k0 + t + 4]);
                } else {
                    bf[nt][0] = __float_as_uint(Bs[(k0 + t    ) * 136 + col]);
                    bf[nt][1] = __float_as_uint(Bs[(k0 + t + 4) * 136 + col]);
                }
            }
#pragma unroll
            for (int mt = 0; mt < 4; mt++)
#pragma unroll
                for (int nt = 0; nt < 4; nt++)
                    asm volatile(
                        "mma.sync.aligned.m16n8k8.row.col.f32.tf32.tf32.f32 "
                        "{%0,%1,%2,%3}, {%4,%5,%6,%7}, {%8,%9}, {%0,%1,%2,%3};"
                        : "+f"(acc[mt][nt][0]), "+f"(acc[mt][nt][1]),
                          "+f"(acc[mt][nt][2]), "+f"(acc[mt][nt][3])
                        : "r"(af[mt][0]), "r"(af[mt][1]), "r"(af[mt][2]), "r"(af[mt][3]),
                          "r"(bf[nt][0]), "r"(bf[nt][1]));
        }
        __syncthreads();
    }

    // --- writeback (fp32) ---
#pragma unroll
    for (int mt = 0; mt < 4; mt++) {
        int row = wm + mt * 16 + g;
#pragma unroll
        for (int nt = 0; nt < 4; nt++) {
            int col = wn + nt * 8 + 2 * t;
            *(float2*)(Cb + (size_t)row       * ldc + col) =
                make_float2(acc[mt][nt][0], acc[mt][nt][1]);
            *(float2*)(Cb + (size_t)(row + 8) * ldc + col) =
                make_float2(acc[mt][nt][2], acc[mt][nt][3]);
        }
    }
}

// ---------------------------------------------------------------------------
// Causal softmax over scores, row-resident in registers (1 read + 1 write).
// One block (256 thr) per row. Applies 1/sqrt(d) scale, masks j>i, zero-fills
// the padded tail of the diagonal 128-block so P*V can read full blocks.
// ---------------------------------------------------------------------------
__global__ void softmax_causal()
{
    const int rid  = blockIdx.x;
    const int bh   = rid >> 11;       // / 2048
    const int i    = rid & 2047;
    float* row = g_att + (size_t)bh * TQ * TQ + (size_t)i * TQ;

    const int n    = i + 1;
    const int npad = ((i >> 7) + 1) << 7;      // round (i+1) up to 128
    const float scale = 0.08838834764831844f;  // 1/sqrt(128)

    float loc[8];
    float m = -3.4e38f;
#pragma unroll
    for (int it = 0; it < 8; it++) {
        int j = threadIdx.x + it * 256;
        loc[it] = (j < n) ? row[j] : -3.4e38f;
        m = fmaxf(m, loc[it]);
    }

    __shared__ float sh[8];
    __shared__ float bval;
#pragma unroll
    for (int o = 16; o; o >>= 1) m = fmaxf(m, __shfl_xor_sync(0xffffffffu, m, o));
    if ((threadIdx.x & 31) == 0) sh[threadIdx.x >> 5] = m;
    __syncthreads();
    if (threadIdx.x == 0) {
        float mm = sh[0];
#pragma unroll
        for (int w = 1; w < 8; w++) mm = fmaxf(mm, sh[w]);
        bval = mm;
    }
    __syncthreads();
    m = bval;

    float s = 0.f;
#pragma unroll
    for (int it = 0; it < 8; it++) {
        int j = threadIdx.x + it * 256;
        float e = (j < n) ? __expf((loc[it] - m) * scale) : 0.f;
        loc[it] = e;
        s += e;
    }
    __syncthreads();
#pragma unroll
    for (int o = 16; o; o >>= 1) s += __shfl_xor_sync(0xffffffffu, s, o);
    if ((threadIdx.x & 31) == 0) sh[threadIdx.x >> 5] = s;
    __syncthreads();
    if (threadIdx.x == 0) {
        float ss = 0.f;
#pragma unroll
        for (int w = 0; w < 8; w++) ss += sh[w];
        bval = ss;
    }
    __syncthreads();
    const float inv = 1.f / bval;

#pragma unroll
    for (int it = 0; it < 8; it++) {
        int j = threadIdx.x + it * 256;
        if (j < npad) row[j] = loc[it] * inv;   // loc==0 for j in [n,npad)
    }
}

// ---------------------------------------------------------------------------
extern "C" void kernel_launch(void* const* d_in, const int* in_sizes, int n_in,
                              void* d_out, int out_size)
{
    (void)in_sizes; (void)n_in; (void)out_size;
    const float* x  = (const float*)d_in[0];  // [4,2048,2048]
    const float* Wa = (const float*)d_in[1];  // [6144,2048]
    const float* Wp = (const float*)d_in[2];  // [2048,2048]
    float*       y  = (float*)d_out;          // [4,2048,2048]

    float *qkv, *att, *out;
    cudaGetSymbolAddress((void**)&qkv, g_qkv);
    cudaGetSymbolAddress((void**)&att, g_att);
    cudaGetSymbolAddress((void**)&out, g_out);

    const dim3 blk(256);
    const size_t sQ = (size_t)TQ * C3;          // qkv per-batch stride
    const size_t sS = (size_t)TQ * TQ;          // scores per-head stride

    // 1) qkv = x @ W_attn^T         M=8192 N=6144 K=2048
    gemm_tc<true, false, false><<<dim3(48, 64, 1), blk>>>(
        x, CH, 0, 0, Wa, CH, 0, 0, qkv, C3, 0, 0, CH);

    // 2) S[b,h] = Q @ K^T (causal block skip)   per (b,h): M=N=2048, K=128
    gemm_tc<true, true, false><<<dim3(16, 16, BATCH * NHEAD), blk>>>(
        qkv,        C3, sQ, HDIM,
        qkv + CH,   C3, sQ, HDIM,
        att,        TQ, (size_t)NHEAD * sS, sS,
        HDIM);

    // 3) causal softmax (scale 1/sqrt(d)) in place
    softmax_causal<<<BATCH * NHEAD * TQ, blk>>>();

    // 4) O[b,h] = P @ V (K truncated per q-block)  per (b,h): M=2048 N=128 K<=2048
    gemm_tc<false, false, true><<<dim3(1, 16, BATCH * NHEAD), blk>>>(
        att,          TQ, (size_t)NHEAD * sS, sS,
        qkv + 2 * CH, C3, sQ, HDIM,
        out,          CH, (size_t)TQ * CH, HDIM,
        TQ);

    // 5) y = out @ W_proj^T         M=8192 N=2048 K=2048
    gemm_tc<true, false, false><<<dim3(16, 64, 1), blk>>>(
        out, CH, 0, 0, Wp, CH, 0, 0, y, CH, 0, 0, CH);
}

// round 10
// speedup vs baseline: 2.3244x; 2.3244x over previous
#include <cuda_runtime.h>
#include <cuda_fp16.h>
#include <cstdint>

// Problem shape (fixed): B=4, T=2048, C=2048, H=16, d=128
#define BATCH 4
#define TQ    2048
#define CH    2048
#define NHEAD 16
#define HDIM  128
#define C3    6144
#define KC    64          // K halves per pipeline stage
#define NSTAGE 3
#define SMEM_BYTES (NSTAGE * 32768)   // 3 x (A 16KB + B 16KB)

// ---- scratch (device globals; no allocation allowed) ----
__device__ __half g_xh  [(size_t)BATCH * TQ * CH];            // 67 MB
__device__ __half g_wah [(size_t)C3 * CH];                    // 25 MB
__device__ __half g_wph [(size_t)CH * CH];                    //  8 MB
__device__ __half g_qkvh[(size_t)BATCH * TQ * C3];            // 100 MB
__device__ __half g_atth[(size_t)BATCH * NHEAD * TQ * TQ];    // 512 MB
__device__ __half g_outh[(size_t)BATCH * TQ * CH];            // 67 MB
__device__ __half g_vth [(size_t)BATCH * NHEAD * HDIM * TQ];  // 67 MB

static __device__ __forceinline__ uint32_t su32(const void* p) {
    uint32_t a;
    asm("{ .reg .u64 t; cvta.to.shared.u64 t, %1; cvt.u32.u64 %0, t; }" : "=r"(a) : "l"(p));
    return a;
}
#define CPA(d, s) asm volatile("cp.async.cg.shared.global [%0], [%1], 16;" \
    :: "r"(d), "l"(__cvta_generic_to_global(s)) : "memory")
#define CPCOMMIT() asm volatile("cp.async.commit_group;" ::: "memory")
#define CPWAIT1()  asm volatile("cp.async.wait_group 1;" ::: "memory")
#define CPWAIT0()  asm volatile("cp.async.wait_group 0;" ::: "memory")

// ---------------------------------------------------------------------------
// f16 tensor-core NT GEMM:  C[M,N] = A[M,K] * B[N,K]^T   (fp32 accumulate)
// CTA tile 128x128, KC=64 halves/stage, 3-stage cp.async pipeline,
// ldmatrix fragment loads from swizzled smem.
// blockIdx.z batches (b,h) via strides sX1 (b) / sX2 (h).
// CSKIP: skip blocks with bx > by (causal upper).  CK: Keff=(by+1)*128 (P*V).
// OUTF16: write C as f16 (else f32).
// ---------------------------------------------------------------------------
template<bool CSKIP, bool CK, bool OUTF16>
__global__ void __launch_bounds__(256, 2)
gemm_h(const __half* __restrict__ A, int lda, size_t sA1, size_t sA2,
       const __half* __restrict__ B, int ldb, size_t sB1, size_t sB2,
       void* __restrict__ Cv, int ldc, size_t sC1, size_t sC2, int K)
{
    if (CSKIP && blockIdx.x > blockIdx.y) return;
    extern __shared__ char smem[];
    const uint32_t smb = su32(smem);

    const int tid = threadIdx.x, wid = tid >> 5, lane = tid & 31;
    const int zb = (int)blockIdx.z >> 4, zh = (int)blockIdx.z & 15;
    const __half* Ab = A + zb * sA1 + zh * sA2 + (size_t)blockIdx.y * 128 * lda;
    const __half* Bb = B + zb * sB1 + zh * sB2 + (size_t)blockIdx.x * 128 * ldb;
    const int Keff = CK ? ((int)blockIdx.y + 1) * 128 : K;
    const int nch  = Keff / KC;

    // fill mapping: 128 rows x 4 x 16B chunks per tensor per thread
    const int fr = tid >> 3;          // row 0..31 (+32 per iter)
    const int fc = tid & 7;           // 16B chunk 0..7

    // ldmatrix per-lane geometry
    const int rA   = (lane & 7) + ((lane >> 3) & 1) * 8;  // 0..15
    const int ksel = lane >> 4;                            // 0/1
    const int wm   = (wid & 1) * 64;
    const int wn   = (wid >> 1) * 32;

    float acc[4][4][4];
#pragma unroll
    for (int i = 0; i < 4; i++)
#pragma unroll
        for (int j = 0; j < 4; j++)
#pragma unroll
            for (int r = 0; r < 4; r++) acc[i][j][r] = 0.f;

    // stage issuer
    auto issue = [&](int ch) {
        const uint32_t sa = smb + (ch % NSTAGE) * 32768;
        const uint32_t sb = sa + 16384;
        const __half* ga = Ab + ch * KC;
        const __half* gb = Bb + ch * KC;
#pragma unroll
        for (int it = 0; it < 4; it++) {
            const int r = fr + it * 32;
            const uint32_t sw = (uint32_t)((fc ^ (r & 7)) << 4);
            CPA(sa + r * 128 + sw, ga + (size_t)r * lda + fc * 8);
            CPA(sb + r * 128 + sw, gb + (size_t)r * ldb + fc * 8);
        }
    };

    issue(0); CPCOMMIT();
    if (nch > 1) { issue(1); CPCOMMIT(); }

    for (int i = 0; i < nch; i++) {
        // real groups committed so far = min(i+2, nch); need groups 0..i done:
        //   allowed pending = 1 for i < nch-1, 0 for the last iteration.
        if (i == nch - 1) CPWAIT0(); else CPWAIT1();
        __syncthreads();
        if (i + 2 < nch) { issue(i + 2); CPCOMMIT(); }

        const uint32_t sa = smb + (i % NSTAGE) * 32768;
        const uint32_t sb = sa + 16384;
#pragma unroll
        for (int kk = 0; kk < 4; kk++) {
            const uint32_t col = (uint32_t)(((kk * 2 + ksel) ^ (rA & 7)) << 4);
            uint32_t a[4][4];
#pragma unroll
            for (int mt = 0; mt < 4; mt++) {
                const uint32_t ad = sa + (uint32_t)(wm + mt * 16 + rA) * 128 + col;
                asm volatile("ldmatrix.sync.aligned.m8n8.x4.shared.b16 {%0,%1,%2,%3}, [%4];"
                    : "=r"(a[mt][0]), "=r"(a[mt][1]), "=r"(a[mt][2]), "=r"(a[mt][3])
                    : "r"(ad));
            }
            uint32_t b[4][2];
#pragma unroll
            for (int pr = 0; pr < 2; pr++) {
                const uint32_t bd = sb + (uint32_t)(wn + pr * 16 + rA) * 128 + col;
                uint32_t r0, r1, r2, r3;
                asm volatile("ldmatrix.sync.aligned.m8n8.x4.shared.b16 {%0,%1,%2,%3}, [%4];"
                    : "=r"(r0), "=r"(r1), "=r"(r2), "=r"(r3) : "r"(bd));
                b[pr * 2][0] = r0; b[pr * 2 + 1][0] = r1;
                b[pr * 2][1] = r2; b[pr * 2 + 1][1] = r3;
            }
#pragma unroll
            for (int mt = 0; mt < 4; mt++)
#pragma unroll
                for (int nt = 0; nt < 4; nt++)
                    asm volatile(
                        "mma.sync.aligned.m16n8k16.row.col.f32.f16.f16.f32 "
                        "{%0,%1,%2,%3}, {%4,%5,%6,%7}, {%8,%9}, {%0,%1,%2,%3};"
                        : "+f"(acc[mt][nt][0]), "+f"(acc[mt][nt][1]),
                          "+f"(acc[mt][nt][2]), "+f"(acc[mt][nt][3])
                        : "r"(a[mt][0]), "r"(a[mt][1]), "r"(a[mt][2]), "r"(a[mt][3]),
                          "r"(b[nt][0]), "r"(b[nt][1]));
        }
        __syncthreads();
    }

    const int g = lane >> 2, t = lane & 3;
    if (OUTF16) {
        __half* Cb = (__half*)Cv + zb * sC1 + zh * sC2
                   + (size_t)blockIdx.y * 128 * ldc + (size_t)blockIdx.x * 128;
        __half* eb = (__half*)smem;    // [128][136]  (272B row stride: 16B-aligned)
#pragma unroll
        for (int mt = 0; mt < 4; mt++) {
            const int r0 = wm + mt * 16 + g;
#pragma unroll
            for (int nt = 0; nt < 4; nt++) {
                const int c0 = wn + nt * 8 + 2 * t;
                *(__half2*)&eb[r0 * 136 + c0]       = __floats2half2_rn(acc[mt][nt][0], acc[mt][nt][1]);
                *(__half2*)&eb[(r0 + 8) * 136 + c0] = __floats2half2_rn(acc[mt][nt][2], acc[mt][nt][3]);
            }
        }
        __syncthreads();
        // full tile writeback: 128 rows x 16 chunks of 8 halves = 2048 chunks
#pragma unroll
        for (int it = 0; it < 8; it++) {
            const int idx = tid + it * 256;
            const int r = idx >> 4, c = idx & 15;
            uint4 v = *(const uint4*)&eb[r * 136 + c * 8];
            *(uint4*)(Cb + (size_t)r * ldc + c * 8) = v;
        }
    } else {
        float* Cb = (float*)Cv + zb * sC1 + zh * sC2
                  + (size_t)blockIdx.y * 128 * ldc + (size_t)blockIdx.x * 128;
#pragma unroll
        for (int mt = 0; mt < 4; mt++) {
            const int r0 = wm + mt * 16 + g;
#pragma unroll
            for (int nt = 0; nt < 4; nt++) {
                const int c0 = wn + nt * 8 + 2 * t;
                *(float2*)(Cb + (size_t)r0 * ldc + c0)       = make_float2(acc[mt][nt][0], acc[mt][nt][1]);
                *(float2*)(Cb + (size_t)(r0 + 8) * ldc + c0) = make_float2(acc[mt][nt][2], acc[mt][nt][3]);
            }
        }
    }
}

// ---------------------------------------------------------------------------
// fp32 -> f16 conversion (vectorized by 4)
// ---------------------------------------------------------------------------
__global__ void f2h(const float* __restrict__ s, __half* __restrict__ d, int n4)
{
    int i = blockIdx.x * blockDim.x + threadIdx.x;
    if (i < n4) {
        float4 v = ((const float4*)s)[i];
        ((__half2*)d)[2 * i]     = __floats2half2_rn(v.x, v.y);
        ((__half2*)d)[2 * i + 1] = __floats2half2_rn(v.z, v.w);
    }
}

// ---------------------------------------------------------------------------
// V transpose: per (b,h), V[t][d] -> Vt[d][t]   (f16)
// ---------------------------------------------------------------------------
__global__ void transV()
{
    __shared__ __half s[32][33];
    const int z = blockIdx.z, b = z >> 4, h = z & 15;
    const __half* src = g_qkvh + (size_t)b * TQ * C3 + 2 * CH + h * HDIM;
    __half* dst = g_vth + (size_t)z * HDIM * TQ;
    const int t0 = blockIdx.x * 32, d0 = blockIdx.y * 32;
    const int tx = threadIdx.x, ty = threadIdx.y;
#pragma unroll
    for (int i = 0; i < 32; i += 8)
        s[ty + i][tx] = src[(size_t)(t0 + ty + i) * C3 + d0 + tx];
    __syncthreads();
#pragma unroll
    for (int i = 0; i < 32; i += 8)
        dst[(size_t)(d0 + ty + i) * TQ + t0 + tx] = s[tx][ty + i];
}

// ---------------------------------------------------------------------------
// Causal softmax on f16 scores, row-resident. Applies 1/sqrt(d), masks j>i,
// zero-fills padded tail of the diagonal 128-block, writes f16 P.
// ---------------------------------------------------------------------------
__global__ void softmax_h()
{
    const int rid = blockIdx.x;
    const int bh  = rid >> 11;
    const int i   = rid & 2047;
    __half2* row2 = (__half2*)(g_atth + (size_t)bh * TQ * TQ + (size_t)i * TQ);

    const int n     = i + 1;
    const int npad2 = (((i >> 7) + 1) << 7) >> 1;     // half2 count to write
    const float scale = 0.08838834764831844f;          // 1/sqrt(128)

    float2 loc[4];
    float m = -3.4e38f;
#pragma unroll
    for (int it = 0; it < 4; it++) {
        const int j2 = threadIdx.x + it * 256;
        __half2 h = row2[j2];
        float2 v;
        v.x = (2 * j2     < n) ? __low2float(h)  : -3.4e38f;
        v.y = (2 * j2 + 1 < n) ? __high2float(h) : -3.4e38f;
        loc[it] = v;
        m = fmaxf(m, fmaxf(v.x, v.y));
    }

    __shared__ float sh[8];
    __shared__ float bval;
#pragma unroll
    for (int o = 16; o; o >>= 1) m = fmaxf(m, __shfl_xor_sync(0xffffffffu, m, o));
    if ((threadIdx.x & 31) == 0) sh[threadIdx.x >> 5] = m;
    __syncthreads();
    if (threadIdx.x == 0) {
        float mm = sh[0];
#pragma unroll
        for (int w = 1; w < 8; w++) mm = fmaxf(mm, sh[w]);
        bval = mm;
    }
    __syncthreads();
    m = bval;

    float s = 0.f;
#pragma unroll
    for (int it = 0; it < 4; it++) {
        const int j2 = threadIdx.x + it * 256;
        float e0 = (2 * j2     < n) ? __expf((loc[it].x - m) * scale) : 0.f;
        float e1 = (2 * j2 + 1 < n) ? __expf((loc[it].y - m) * scale) : 0.f;
        loc[it].x = e0; loc[it].y = e1;
        s += e0 + e1;
    }
    __syncthreads();
#pragma unroll
    for (int o = 16; o; o >>= 1) s += __shfl_xor_sync(0xffffffffu, s, o);
    if ((threadIdx.x & 31) == 0) sh[threadIdx.x >> 5] = s;
    __syncthreads();
    if (threadIdx.x == 0) {
        float ss = 0.f;
#pragma unroll
        for (int w = 0; w < 8; w++) ss += sh[w];
        bval = ss;
    }
    __syncthreads();
    const float inv = 1.f / bval;

#pragma unroll
    for (int it = 0; it < 4; it++) {
        const int j2 = threadIdx.x + it * 256;
        if (j2 < npad2)
            row2[j2] = __floats2half2_rn(loc[it].x * inv, loc[it].y * inv);
    }
}

// ---------------------------------------------------------------------------
extern "C" void kernel_launch(void* const* d_in, const int* in_sizes, int n_in,
                              void* d_out, int out_size)
{
    (void)in_sizes; (void)n_in; (void)out_size;
    const float* x  = (const float*)d_in[0];
    const float* Wa = (const float*)d_in[1];
    const float* Wp = (const float*)d_in[2];
    float*       y  = (float*)d_out;

    __half *xh, *wah, *wph, *qkvh, *atth, *outh, *vth;
    cudaGetSymbolAddress((void**)&xh,   g_xh);
    cudaGetSymbolAddress((void**)&wah,  g_wah);
    cudaGetSymbolAddress((void**)&wph,  g_wph);
    cudaGetSymbolAddress((void**)&qkvh, g_qkvh);
    cudaGetSymbolAddress((void**)&atth, g_atth);
    cudaGetSymbolAddress((void**)&outh, g_outh);
    cudaGetSymbolAddress((void**)&vth,  g_vth);

    cudaFuncSetAttribute(gemm_h<false, false, true >, cudaFuncAttributeMaxDynamicSharedMemorySize, SMEM_BYTES);
    cudaFuncSetAttribute(gemm_h<true,  false, true >, cudaFuncAttributeMaxDynamicSharedMemorySize, SMEM_BYTES);
    cudaFuncSetAttribute(gemm_h<false, true,  true >, cudaFuncAttributeMaxDynamicSharedMemorySize, SMEM_BYTES);
    cudaFuncSetAttribute(gemm_h<false, false, false>, cudaFuncAttributeMaxDynamicSharedMemorySize, SMEM_BYTES);

    // 0) fp32 -> f16 input conversion
    f2h<<<16384, 256>>>(x,  xh,  (BATCH * TQ * CH) / 4);
    f2h<<<12288, 256>>>(Wa, wah, (C3 * CH) / 4);
    f2h<<< 4096, 256>>>(Wp, wph, (CH * CH) / 4);

    const size_t sQ = (size_t)TQ * C3;
    const size_t sS = (size_t)TQ * TQ;

    // 1) qkv = x @ W_attn^T        M=8192 N=6144 K=2048  (f16 out)
    gemm_h<false, false, true><<<dim3(48, 64, 1), 256, SMEM_BYTES>>>(
        xh, CH, 0, 0, wah, CH, 0, 0, qkvh, C3, 0, 0, CH);

    // 1b) V^T per (b,h)
    transV<<<dim3(64, 4, 64), dim3(32, 8)>>>();

    // 2) S = Q @ K^T (causal block skip), per bh M=N=2048 K=128
    gemm_h<true, false, true><<<dim3(16, 16, BATCH * NHEAD), 256, SMEM_BYTES>>>(
        qkvh,      C3, sQ, HDIM,
        qkvh + CH, C3, sQ, HDIM,
        atth,      TQ, (size_t)NHEAD * sS, sS, HDIM);

    // 3) causal softmax in place (f16)
    softmax_h<<<BATCH * NHEAD * TQ, 256>>>();

    // 4) O = P @ V   (B = V^T, K truncated per q-block)
    gemm_h<false, true, true><<<dim3(1, 16, BATCH * NHEAD), 256, SMEM_BYTES>>>(
        atth, TQ, (size_t)NHEAD * sS, sS,
        vth,  TQ, (size_t)NHEAD * HDIM * TQ, (size_t)HDIM * TQ,
        outh, CH, (size_t)TQ * CH, HDIM, TQ);

    // 5) y = out @ W_proj^T        M=8192 N=2048 K=2048  (f32 out)
    gemm_h<false, false, false><<<dim3(16, 64, 1), 256, SMEM_BYTES>>>(
        outh, CH, 0, 0, wph, CH, 0, 0, y, CH, 0, 0, CH);
}

// round 14
// speedup vs baseline: 2.7359x; 1.1770x over previous
#include <cuda_runtime.h>
#include <cuda_fp16.h>
#include <cstdint>

// Problem shape (fixed): B=4, T=2048, C=2048, H=16, d=128
#define BATCH 4
#define TQ    2048
#define CH    2048
#define NHEAD 16
#define HDIM  128
#define C3    6144
#define KC    64          // K halves per pipeline stage (GEMM)
#define NSTAGE 3
#define SMEM_BYTES (NSTAGE * 32768)   // 3 x (A 16KB + B 16KB)

// Flash smem layout (dynamic): Q | K(2 stages) | Vt(2 stages) | P
#define FSM_Q 0
#define FSM_K 32768
#define FSM_V (3 * 32768)
#define FSM_P (5 * 32768)
#define FSM_TOTAL (5 * 32768 + 128 * 272)   // 198656

// ---- scratch (device globals; no allocation allowed) ----
__device__ __half g_xh  [(size_t)BATCH * TQ * CH];            // 67 MB
__device__ __half g_wah [(size_t)C3 * CH];                    // 25 MB
__device__ __half g_wph [(size_t)CH * CH];                    //  8 MB
__device__ __half g_qkvh[(size_t)BATCH * TQ * C3];            // 100 MB
__device__ __half g_outh[(size_t)BATCH * TQ * CH];            // 67 MB
__device__ __half g_vth [(size_t)BATCH * NHEAD * HDIM * TQ];  // 67 MB (V^T per bh)

static __device__ __forceinline__ uint32_t su32(const void* p) {
    uint32_t a;
    asm("{ .reg .u64 t; cvta.to.shared.u64 t, %1; cvt.u32.u64 %0, t; }" : "=r"(a) : "l"(p));
    return a;
}
#define CPA(d, s) asm volatile("cp.async.cg.shared.global [%0], [%1], 16;" \
    :: "r"(d), "l"(__cvta_generic_to_global(s)) : "memory")
#define CPCOMMIT() asm volatile("cp.async.commit_group;" ::: "memory")
#define CPWAIT1()  asm volatile("cp.async.wait_group 1;" ::: "memory")
#define CPWAIT0()  asm volatile("cp.async.wait_group 0;" ::: "memory")

#define LDSM4(r0, r1, r2, r3, ad) \
    asm volatile("ldmatrix.sync.aligned.m8n8.x4.shared.b16 {%0,%1,%2,%3}, [%4];" \
        : "=r"(r0), "=r"(r1), "=r"(r2), "=r"(r3) : "r"(ad))

#define MMA16816(acc, af, bf) \
    asm volatile("mma.sync.aligned.m16n8k16.row.col.f32.f16.f16.f32 " \
        "{%0,%1,%2,%3}, {%4,%5,%6,%7}, {%8,%9}, {%0,%1,%2,%3};" \
        : "+f"((acc)[0]), "+f"((acc)[1]), "+f"((acc)[2]), "+f"((acc)[3]) \
        : "r"((af)[0]), "r"((af)[1]), "r"((af)[2]), "r"((af)[3]), \
          "r"((bf)[0]), "r"((bf)[1]))

// ---------------------------------------------------------------------------
// f16 tensor-core NT GEMM:  C[M,N] = A[M,K] * B[N,K]^T   (fp32 accumulate)
// CTA tile 128x128, KC=64 halves/stage, 3-stage cp.async pipeline.
// (validated in round 10)
// ---------------------------------------------------------------------------
template<bool OUTF16>
__global__ void __launch_bounds__(256, 2)
gemm_h(const __half* __restrict__ A, int lda,
       const __half* __restrict__ B, int ldb,
       void* __restrict__ Cv, int ldc, int K)
{
    extern __shared__ char smem[];
    const uint32_t smb = su32(smem);

    const int tid = threadIdx.x, wid = tid >> 5, lane = tid & 31;
    const __half* Ab = A + (size_t)blockIdx.y * 128 * lda;
    const __half* Bb = B + (size_t)blockIdx.x * 128 * ldb;
    const int nch = K / KC;

    const int fr = tid >> 3;
    const int fc = tid & 7;
    const int rA   = (lane & 7) + ((lane >> 3) & 1) * 8;
    const int ksel = lane >> 4;
    const int wm   = (wid & 1) * 64;
    const int wn   = (wid >> 1) * 32;

    float acc[4][4][4];
#pragma unroll
    for (int i = 0; i < 4; i++)
#pragma unroll
        for (int j = 0; j < 4; j++)
#pragma unroll
            for (int r = 0; r < 4; r++) acc[i][j][r] = 0.f;

    auto issue = [&](int ch) {
        const uint32_t sa = smb + (ch % NSTAGE) * 32768;
        const uint32_t sb = sa + 16384;
        const __half* ga = Ab + ch * KC;
        const __half* gb = Bb + ch * KC;
#pragma unroll
        for (int it = 0; it < 4; it++) {
            const int r = fr + it * 32;
            const uint32_t sw = (uint32_t)((fc ^ (r & 7)) << 4);
            CPA(sa + r * 128 + sw, ga + (size_t)r * lda + fc * 8);
            CPA(sb + r * 128 + sw, gb + (size_t)r * ldb + fc * 8);
        }
    };

    issue(0); CPCOMMIT();
    if (nch > 1) { issue(1); CPCOMMIT(); }

    for (int i = 0; i < nch; i++) {
        if (i == nch - 1) CPWAIT0(); else CPWAIT1();
        __syncthreads();
        if (i + 2 < nch) { issue(i + 2); CPCOMMIT(); }

        const uint32_t sa = smb + (i % NSTAGE) * 32768;
        const uint32_t sb = sa + 16384;
#pragma unroll
        for (int kk = 0; kk < 4; kk++) {
            const uint32_t col = (uint32_t)(((kk * 2 + ksel) ^ (rA & 7)) << 4);
            uint32_t a[4][4];
#pragma unroll
            for (int mt = 0; mt < 4; mt++)
                LDSM4(a[mt][0], a[mt][1], a[mt][2], a[mt][3],
                      sa + (uint32_t)(wm + mt * 16 + rA) * 128 + col);
            uint32_t b[4][2];
#pragma unroll
            for (int pr = 0; pr < 2; pr++) {
                uint32_t r0, r1, r2, r3;
                LDSM4(r0, r1, r2, r3, sb + (uint32_t)(wn + pr * 16 + rA) * 128 + col);
                b[pr * 2][0] = r0; b[pr * 2 + 1][0] = r1;
                b[pr * 2][1] = r2; b[pr * 2 + 1][1] = r3;
            }
#pragma unroll
            for (int mt = 0; mt < 4; mt++)
#pragma unroll
                for (int nt = 0; nt < 4; nt++)
                    MMA16816(acc[mt][nt], a[mt], b[nt]);
        }
        __syncthreads();
    }

    const int g = lane >> 2, t = lane & 3;
    if (OUTF16) {
        __half* Cb = (__half*)Cv + (size_t)blockIdx.y * 128 * ldc + (size_t)blockIdx.x * 128;
        __half* eb = (__half*)smem;    // [128][136]
#pragma unroll
        for (int mt = 0; mt < 4; mt++) {
            const int r0 = wm + mt * 16 + g;
#pragma unroll
            for (int nt = 0; nt < 4; nt++) {
                const int c0 = wn + nt * 8 + 2 * t;
                *(__half2*)&eb[r0 * 136 + c0]       = __floats2half2_rn(acc[mt][nt][0], acc[mt][nt][1]);
                *(__half2*)&eb[(r0 + 8) * 136 + c0] = __floats2half2_rn(acc[mt][nt][2], acc[mt][nt][3]);
            }
        }
        __syncthreads();
#pragma unroll
        for (int it = 0; it < 8; it++) {
            const int idx = tid + it * 256;
            const int r = idx >> 4, c = idx & 15;
            uint4 v = *(const uint4*)&eb[r * 136 + c * 8];
            *(uint4*)(Cb + (size_t)r * ldc + c * 8) = v;
        }
    } else {
        float* Cb = (float*)Cv + (size_t)blockIdx.y * 128 * ldc + (size_t)blockIdx.x * 128;
#pragma unroll
        for (int mt = 0; mt < 4; mt++) {
            const int r0 = wm + mt * 16 + g;
#pragma unroll
            for (int nt = 0; nt < 4; nt++) {
                const int c0 = wn + nt * 8 + 2 * t;
                *(float2*)(Cb + (size_t)r0 * ldc + c0)       = make_float2(acc[mt][nt][0], acc[mt][nt][1]);
                *(float2*)(Cb + (size_t)(r0 + 8) * ldc + c0) = make_float2(acc[mt][nt][2], acc[mt][nt][3]);
            }
        }
    }
}

// ---------------------------------------------------------------------------
// Fused flash attention: per CTA one 128-row q-block of one (b,h).
// Streams K/Vt 128-blocks (j <= i), online softmax, O accumulated in regs.
// ---------------------------------------------------------------------------
__global__ void __launch_bounds__(256, 1)
flash_attn()
{
    extern __shared__ char smem[];
    const uint32_t smb = su32(smem);
    __shared__ float sredm[128][4];
    __shared__ float sreds[128][4];

    const int tid = threadIdx.x, wid = tid >> 5, lane = tid & 31;
    const int ib = 15 - (int)blockIdx.x;           // heavy q-blocks first
    const int z  = (int)blockIdx.y;
    const int zb = z >> 4, zh = z & 15;

    const __half* gQ  = g_qkvh + (size_t)zb * TQ * C3 + zh * HDIM + (size_t)ib * 128 * C3;
    const __half* gK  = g_qkvh + (size_t)zb * TQ * C3 + CH + zh * HDIM;
    const __half* gVt = g_vth + (size_t)z * HDIM * TQ;

    const int fr = tid >> 3, fc = tid & 7;
    const int rA   = (lane & 7) + ((lane >> 3) & 1) * 8;
    const int ksel = lane >> 4;
    const int wm   = (wid & 1) * 64;
    const int wn   = (wid >> 1) * 32;
    const int g = lane >> 2, t = lane & 3;
    const int nw = wid >> 1;
    const float scale = 0.08838834764831844f;      // 1/sqrt(128)

    auto issueKV = [&](int jb, int s) {
        const uint32_t kk = smb + FSM_K + s * 32768;
        const uint32_t vv = smb + FSM_V + s * 32768;
#pragma unroll
        for (int ch = 0; ch < 2; ch++)
#pragma unroll
            for (int it = 0; it < 4; it++) {
                const int r = fr + it * 32;
                const uint32_t sw = (uint32_t)((fc ^ (r & 7)) << 4);
                CPA(kk + ch * 16384 + r * 128 + sw,
                    gK + (size_t)(jb * 128 + r) * C3 + ch * 64 + fc * 8);
                CPA(vv + ch * 16384 + r * 128 + sw,
                    gVt + (size_t)r * TQ + jb * 128 + ch * 64 + fc * 8);
            }
    };

    // one-time Q load + first K/V block (one commit group)
    {
#pragma unroll
        for (int ch = 0; ch < 2; ch++)
#pragma unroll
            for (int it = 0; it < 4; it++) {
                const int r = fr + it * 32;
                const uint32_t sw = (uint32_t)((fc ^ (r & 7)) << 4);
                CPA(smb + FSM_Q + ch * 16384 + r * 128 + sw,
                    gQ + (size_t)r * C3 + ch * 64 + fc * 8);
            }
        issueKV(0, 0);
        CPCOMMIT();
    }

    float acc_o[4][4][4];
#pragma unroll
    for (int i = 0; i < 4; i++)
#pragma unroll
        for (int j = 0; j < 4; j++)
#pragma unroll
            for (int r = 0; r < 4; r++) acc_o[i][j][r] = 0.f;
    float m_i[8], l_i[8];
#pragma unroll
    for (int r = 0; r < 8; r++) { m_i[r] = -1e30f; l_i[r] = 0.f; }

    for (int jb = 0; jb <= ib; jb++) {
        const int s = jb & 1;
        CPWAIT0();                 // only load(jb) can be pending here
        __syncthreads();           // also fences P/sred/stage reuse from prev iter
        if (jb < ib) { issueKV(jb + 1, s ^ 1); CPCOMMIT(); }

        // ---- S = Q @ K^T (128x128, fp32) ----
        float acc_s[4][4][4];
#pragma unroll
        for (int i = 0; i < 4; i++)
#pragma unroll
            for (int j = 0; j < 4; j++)
#pragma unroll
                for (int r = 0; r < 4; r++) acc_s[i][j][r] = 0.f;

        const uint32_t qb = smb + FSM_Q;
        const uint32_t kb = smb + FSM_K + s * 32768;
#pragma unroll
        for (int ch = 0; ch < 2; ch++)
#pragma unroll
            for (int kk = 0; kk < 4; kk++) {
                const uint32_t col = (uint32_t)(((kk * 2 + ksel) ^ (rA & 7)) << 4);
                uint32_t a[4][4];
#pragma unroll
                for (int mt = 0; mt < 4; mt++)
                    LDSM4(a[mt][0], a[mt][1], a[mt][2], a[mt][3],
                          qb + ch * 16384 + (uint32_t)(wm + mt * 16 + rA) * 128 + col);
                uint32_t b[4][2];
#pragma unroll
                for (int pr = 0; pr < 2; pr++) {
                    uint32_t r0, r1, r2, r3;
                    LDSM4(r0, r1, r2, r3,
                          kb + ch * 16384 + (uint32_t)(wn + pr * 16 + rA) * 128 + col);
                    b[pr * 2][0] = r0; b[pr * 2 + 1][0] = r1;
                    b[pr * 2][1] = r2; b[pr * 2 + 1][1] = r3;
                }
#pragma unroll
                for (int mt = 0; mt < 4; mt++)
#pragma unroll
                    for (int nt = 0; nt < 4; nt++)
                        MMA16816(acc_s[mt][nt], a[mt], b[nt]);
            }

        // ---- causal mask (diagonal block only) ----
        if (jb == ib) {
#pragma unroll
            for (int mt = 0; mt < 4; mt++) {
                const int r0 = wm + mt * 16 + g;
#pragma unroll
                for (int nt = 0; nt < 4; nt++) {
                    const int c0 = wn + nt * 8 + 2 * t;
                    if (c0     > r0    ) acc_s[mt][nt][0] = -1e30f;
                    if (c0 + 1 > r0    ) acc_s[mt][nt][1] = -1e30f;
                    if (c0     > r0 + 8) acc_s[mt][nt][2] = -1e30f;
                    if (c0 + 1 > r0 + 8) acc_s[mt][nt][3] = -1e30f;
                }
            }
        }

        // ---- row max: warp-local (shfl over t) + cross-n-warp via smem ----
#pragma unroll
        for (int mt = 0; mt < 4; mt++)
#pragma unroll
            for (int h = 0; h < 2; h++) {
                float pm = -1e30f;
#pragma unroll
                for (int nt = 0; nt < 4; nt++)
                    pm = fmaxf(pm, fmaxf(acc_s[mt][nt][2 * h], acc_s[mt][nt][2 * h + 1]));
                pm = fmaxf(pm, __shfl_xor_sync(0xffffffffu, pm, 1));
                pm = fmaxf(pm, __shfl_xor_sync(0xffffffffu, pm, 2));
                if (t == 0) sredm[wm + mt * 16 + g + h * 8][nw] = pm;
            }
        __syncthreads();

        float mnew[8];
#pragma unroll
        for (int mt = 0; mt < 4; mt++)
#pragma unroll
            for (int h = 0; h < 2; h++) {
                const int r = wm + mt * 16 + g + h * 8;
                const float mb = fmaxf(fmaxf(sredm[r][0], sredm[r][1]),
                                       fmaxf(sredm[r][2], sredm[r][3]));
                mnew[mt * 2 + h] = fmaxf(m_i[mt * 2 + h], mb);
            }

        // ---- P = exp(scale*(S-mnew)), store f16 to smem, partial row sums ----
#pragma unroll
        for (int mt = 0; mt < 4; mt++)
#pragma unroll
            for (int h = 0; h < 2; h++) {
                const int r = wm + mt * 16 + g + h * 8;
                const float mn = mnew[mt * 2 + h];
                float ps = 0.f;
#pragma unroll
                for (int nt = 0; nt < 4; nt++) {
                    const float e0 = __expf((acc_s[mt][nt][2 * h]     - mn) * scale);
                    const float e1 = __expf((acc_s[mt][nt][2 * h + 1] - mn) * scale);
                    ps += e0 + e1;
                    *(__half2*)(smem + FSM_P + r * 272 + (wn + nt * 8 + 2 * t) * 2) =
                        __floats2half2_rn(e0, e1);
                }
                ps += __shfl_xor_sync(0xffffffffu, ps, 1);
                ps += __shfl_xor_sync(0xffffffffu, ps, 2);
                if (t == 0) sreds[r][nw] = ps;
            }
        __syncthreads();

        // ---- online update: l, m, rescale O ----
#pragma unroll
        for (int mt = 0; mt < 4; mt++)
#pragma unroll
            for (int h = 0; h < 2; h++) {
                const int idx = mt * 2 + h;
                const int r = wm + mt * 16 + g + h * 8;
                const float mn = mnew[idx];
                const float alpha = __expf((m_i[idx] - mn) * scale);
                const float bs = sreds[r][0] + sreds[r][1] + sreds[r][2] + sreds[r][3];
                l_i[idx] = alpha * l_i[idx] + bs;
                m_i[idx] = mn;
#pragma unroll
                for (int nt = 0; nt < 4; nt++) {
                    acc_o[mt][nt][2 * h]     *= alpha;
                    acc_o[mt][nt][2 * h + 1] *= alpha;
                }
            }

        // ---- O += P @ V  (A = P from padded smem, B = Vt tile) ----
        const uint32_t pb = smb + FSM_P;
        const uint32_t vb = smb + FSM_V + s * 32768;
#pragma unroll
        for (int kk = 0; kk < 8; kk++) {
            uint32_t a[4][4];
#pragma unroll
            for (int mt = 0; mt < 4; mt++)
                LDSM4(a[mt][0], a[mt][1], a[mt][2], a[mt][3],
                      pb + (uint32_t)(wm + mt * 16 + rA) * 272 + (kk * 2 + ksel) * 16);
            const uint32_t coln = (uint32_t)((((kk & 3) * 2 + ksel) ^ (rA & 7)) << 4);
            uint32_t b[4][2];
#pragma unroll
            for (int pr = 0; pr < 2; pr++) {
                uint32_t r0, r1, r2, r3;
                LDSM4(r0, r1, r2, r3,
                      vb + (kk >> 2) * 16384 + (uint32_t)(wn + pr * 16 + rA) * 128 + coln);
                b[pr * 2][0] = r0; b[pr * 2 + 1][0] = r1;
                b[pr * 2][1] = r2; b[pr * 2 + 1][1] = r3;
            }
#pragma unroll
            for (int mt = 0; mt < 4; mt++)
#pragma unroll
                for (int nt = 0; nt < 4; nt++)
                    MMA16816(acc_o[mt][nt], a[mt], b[nt]);
        }
    }

    // ---- normalize and write O (f16) ----
    __half* gO = g_outh + (size_t)zb * TQ * CH + (size_t)(ib * 128) * CH + zh * HDIM;
#pragma unroll
    for (int mt = 0; mt < 4; mt++)
#pragma unroll
        for (int h = 0; h < 2; h++) {
            const int idx = mt * 2 + h;
            const int r = wm + mt * 16 + g + h * 8;
            const float inv = 1.f / l_i[idx];
#pragma unroll
            for (int nt = 0; nt < 4; nt++) {
                const int c = wn + nt * 8 + 2 * t;
                *(__half2*)(gO + (size_t)r * CH + c) =
                    __floats2half2_rn(acc_o[mt][nt][2 * h] * inv,
                                      acc_o[mt][nt][2 * h + 1] * inv);
            }
        }
}

// ---------------------------------------------------------------------------
// fp32 -> f16 conversion (vectorized by 4)
// ---------------------------------------------------------------------------
__global__ void f2h(const float* __restrict__ s, __half* __restrict__ d, int n4)
{
    int i = blockIdx.x * blockDim.x + threadIdx.x;
    if (i < n4) {
        float4 v = ((const float4*)s)[i];
        ((__half2*)d)[2 * i]     = __floats2half2_rn(v.x, v.y);
        ((__half2*)d)[2 * i + 1] = __floats2half2_rn(v.z, v.w);
    }
}

// ---------------------------------------------------------------------------
// V transpose: per (b,h), V[t][d] -> Vt[d][t]   (f16)
// ---------------------------------------------------------------------------
__global__ void transV()
{
    __shared__ __half s[32][33];
    const int z = blockIdx.z, b = z >> 4, h = z & 15;
    const __half* src = g_qkvh + (size_t)b * TQ * C3 + 2 * CH + h * HDIM;
    __half* dst = g_vth + (size_t)z * HDIM * TQ;
    const int t0 = blockIdx.x * 32, d0 = blockIdx.y * 32;
    const int tx = threadIdx.x, ty = threadIdx.y;
#pragma unroll
    for (int i = 0; i < 32; i += 8)
        s[ty + i][tx] = src[(size_t)(t0 + ty + i) * C3 + d0 + tx];
    __syncthreads();
#pragma unroll
    for (int i = 0; i < 32; i += 8)
        dst[(size_t)(d0 + ty + i) * TQ + t0 + tx] = s[tx][ty + i];
}

// ---------------------------------------------------------------------------
extern "C" void kernel_launch(void* const* d_in, const int* in_sizes, int n_in,
                              void* d_out, int out_size)
{
    (void)in_sizes; (void)n_in; (void)out_size;
    const float* x  = (const float*)d_in[0];
    const float* Wa = (const float*)d_in[1];
    const float* Wp = (const float*)d_in[2];
    float*       y  = (float*)d_out;

    __half *xh, *wah, *wph, *qkvh, *outh;
    cudaGetSymbolAddress((void**)&xh,   g_xh);
    cudaGetSymbolAddress((void**)&wah,  g_wah);
    cudaGetSymbolAddress((void**)&wph,  g_wph);
    cudaGetSymbolAddress((void**)&qkvh, g_qkvh);
    cudaGetSymbolAddress((void**)&outh, g_outh);

    cudaFuncSetAttribute(gemm_h<true >, cudaFuncAttributeMaxDynamicSharedMemorySize, SMEM_BYTES);
    cudaFuncSetAttribute(gemm_h<false>, cudaFuncAttributeMaxDynamicSharedMemorySize, SMEM_BYTES);
    cudaFuncSetAttribute(flash_attn,    cudaFuncAttributeMaxDynamicSharedMemorySize, FSM_TOTAL);

    // 0) fp32 -> f16 input conversion
    f2h<<<16384, 256>>>(x,  xh,  (BATCH * TQ * CH) / 4);
    f2h<<<12288, 256>>>(Wa, wah, (C3 * CH) / 4);
    f2h<<< 4096, 256>>>(Wp, wph, (CH * CH) / 4);

    // 1) qkv = x @ W_attn^T        M=8192 N=6144 K=2048  (f16 out)
    gemm_h<true><<<dim3(48, 64, 1), 256, SMEM_BYTES>>>(
        xh, CH, wah, CH, qkvh, C3, CH);

    // 1b) V^T per (b,h)
    transV<<<dim3(64, 4, 64), dim3(32, 8)>>>();

    // 2) fused causal attention (QK^T + softmax + PV), O in f16
    flash_attn<<<dim3(16, BATCH * NHEAD), 256, FSM_TOTAL>>>();

    // 3) y = out @ W_proj^T        M=8192 N=2048 K=2048  (f32 out)
    gemm_h<false><<<dim3(16, 64, 1), 256, SMEM_BYTES>>>(
        outh, CH, wph, CH, y, CH, CH);
}